// round 3
// baseline (speedup 1.0000x reference)
#include <cuda_runtime.h>
#include <cuda_bf16.h>
#include <math.h>

// ---------------- problem constants ----------------
#define TT   100      // time steps after conv
#define BB   512      // batch
#define WW   18       // conv output width
#define CC   32       // conv channels
#define FF   576      // WW*CC lstm input features
#define HH   128      // hidden
#define GG   512      // 4*HH gates
#define NC   12       // classes

// ---------------- device scratch ----------------
__device__ float g_seq [TT * BB * FF];
__device__ float g_xp  [TT * BB * GG];
__device__ float g_h1  [TT * BB * HH];
__device__ float g_h2  [TT * BB * HH];
__device__ float g_wattT[HH * HH];
__device__ float g_attn [TT * BB];
__device__ float g_pooled[BB * HH];

__device__ __forceinline__ float sigf(float x) { return 1.0f / (1.0f + expf(-x)); }

// =====================================================================
// Conv: one block per batch image. Whole image in smem (812*40*4=127KB).
// Lane = channel (32). Each warp processes pairs of time steps (t0,t0+1)
// which share 12 of their 28 input rows. Per-channel weights live in
// registers (100 per thread). Patch loads broadcast across the 32 lanes.
// =====================================================================
__global__ void __launch_bounds__(256, 1) conv_kernel(const float* __restrict__ x,
                                                      const float* __restrict__ cw,
                                                      const float* __restrict__ cb) {
    extern __shared__ float s_img[];   // [812][40]
    int b = blockIdx.x;
    int tid = threadIdx.x;
    int wid = tid >> 5, lane = tid & 31;
    int c = lane;

    // load image (coalesced float4)
    const float4* src = (const float4*)(x + (size_t)b * 812 * 40);
    float4* dst = (float4*)s_img;
    for (int i = tid; i < 812 * 10; i += 256) dst[i] = src[i];

    // per-channel weights + bias into registers
    float wr[100];
#pragma unroll
    for (int i = 0; i < 100; i++) wr[i] = __ldg(&cw[c * 100 + i]);
    float bv = __ldg(&cb[c]);
    __syncthreads();

    for (int p = wid; p < 50; p += 8) {          // t0 = 2p, t1 = 2p+1
        int base_row = 16 * p;
        float acc[2][18];
#pragma unroll
        for (int w = 0; w < 18; w++) { acc[0][w] = bv; acc[1][w] = bv; }

#pragma unroll
        for (int rr = 0; rr < 28; rr++) {
            const float* prow = &s_img[(base_row + rr) * 40];
#pragma unroll
            for (int j = 0; j < 40; j++) {
                float pv = prow[j];
#pragma unroll
                for (int kw = 0; kw < 5; kw++) {
                    int d = j - kw;
                    if (d >= 0 && (d & 1) == 0) {
                        int w = d >> 1;
                        if (w < 18) {
                            if (rr < 20) acc[0][w] += wr[rr * 5 + kw] * pv;
                            if (rr >= 8) acc[1][w] += wr[(rr - 8) * 5 + kw] * pv;
                        }
                    }
                }
            }
        }
#pragma unroll
        for (int ts = 0; ts < 2; ts++) {
            int t = 2 * p + ts;
            float* out = &g_seq[((size_t)t * BB + b) * FF];
#pragma unroll
            for (int w = 0; w < 18; w++)
                out[w * 32 + c] = fmaxf(acc[ts][w], 0.0f);
        }
    }
}

// ---------------- generic transpose (used for W_att only) ----------------
__global__ void transpose_kernel(const float* __restrict__ in, float* __restrict__ out,
                                 int rows, int cols) {
    int idx = blockIdx.x * 256 + threadIdx.x;
    if (idx < rows * cols) {
        int r = idx / cols, c = idx % cols;
        out[c * rows + r] = in[idx];
    }
}

// =====================================================================
// fp32 SGEMM: C[M,N] = A[M,K] @ B[N,K]^T + bias0 + bias1
// 128x128 tile, BK=16, 8x8 micro-tile, float4 smem I/O, reg prefetch.
// Requires M%128==0, N%128==0, K%16==0.
// =====================================================================
__global__ void __launch_bounds__(256, 2) gemm128(const float* __restrict__ A,
                                                  const float* __restrict__ Bm,
                                                  const float* __restrict__ bias0,
                                                  const float* __restrict__ bias1,
                                                  float* __restrict__ C,
                                                  int M, int N, int K) {
    __shared__ float As[16][128];
    __shared__ float Bs[16][128];
    int tid = threadIdx.x;
    int tx = tid & 15, ty = tid >> 4;
    int bm = blockIdx.y * 128, bn = blockIdx.x * 128;

    int r0 = tid >> 2, kq = (tid & 3) << 2;
    int r1 = r0 + 64;
    const float* Ap0 = A + (size_t)(bm + r0) * K + kq;
    const float* Ap1 = A + (size_t)(bm + r1) * K + kq;
    const float* Bp0 = Bm + (size_t)(bn + r0) * K + kq;
    const float* Bp1 = Bm + (size_t)(bn + r1) * K + kq;

    float4 a0 = *(const float4*)Ap0;
    float4 a1 = *(const float4*)Ap1;
    float4 b0 = *(const float4*)Bp0;
    float4 b1 = *(const float4*)Bp1;

    float acc[8][8];
#pragma unroll
    for (int i = 0; i < 8; i++)
#pragma unroll
        for (int j = 0; j < 8; j++) acc[i][j] = 0.0f;

    for (int kt = 0; kt < K; kt += 16) {
        As[kq + 0][r0] = a0.x; As[kq + 1][r0] = a0.y; As[kq + 2][r0] = a0.z; As[kq + 3][r0] = a0.w;
        As[kq + 0][r1] = a1.x; As[kq + 1][r1] = a1.y; As[kq + 2][r1] = a1.z; As[kq + 3][r1] = a1.w;
        Bs[kq + 0][r0] = b0.x; Bs[kq + 1][r0] = b0.y; Bs[kq + 2][r0] = b0.z; Bs[kq + 3][r0] = b0.w;
        Bs[kq + 0][r1] = b1.x; Bs[kq + 1][r1] = b1.y; Bs[kq + 2][r1] = b1.z; Bs[kq + 3][r1] = b1.w;
        __syncthreads();

        if (kt + 16 < K) {
            a0 = *(const float4*)(Ap0 + kt + 16);
            a1 = *(const float4*)(Ap1 + kt + 16);
            b0 = *(const float4*)(Bp0 + kt + 16);
            b1 = *(const float4*)(Bp1 + kt + 16);
        }

#pragma unroll
        for (int kk = 0; kk < 16; kk++) {
            float4 x0 = *(const float4*)&As[kk][ty * 8];
            float4 x1 = *(const float4*)&As[kk][ty * 8 + 4];
            float4 y0 = *(const float4*)&Bs[kk][tx * 8];
            float4 y1 = *(const float4*)&Bs[kk][tx * 8 + 4];
            float xa[8] = {x0.x, x0.y, x0.z, x0.w, x1.x, x1.y, x1.z, x1.w};
            float yb[8] = {y0.x, y0.y, y0.z, y0.w, y1.x, y1.y, y1.z, y1.w};
#pragma unroll
            for (int i = 0; i < 8; i++)
#pragma unroll
                for (int j = 0; j < 8; j++) acc[i][j] += xa[i] * yb[j];
        }
        __syncthreads();
    }

    float bc[8];
#pragma unroll
    for (int j = 0; j < 8; j++) {
        int col = bn + tx * 8 + j;
        float v = 0.0f;
        if (bias0) v += bias0[col];
        if (bias1) v += bias1[col];
        bc[j] = v;
    }
#pragma unroll
    for (int i = 0; i < 8; i++) {
        int row = bm + ty * 8 + i;
        float* cp = C + (size_t)row * N + bn + tx * 8;
        float4 o0 = make_float4(acc[i][0] + bc[0], acc[i][1] + bc[1],
                                acc[i][2] + bc[2], acc[i][3] + bc[3]);
        float4 o1 = make_float4(acc[i][4] + bc[4], acc[i][5] + bc[5],
                                acc[i][6] + bc[6], acc[i][7] + bc[7]);
        *(float4*)cp = o0;
        *(float4*)(cp + 4) = o1;
    }
}

// =====================================================================
// LSTM recurrence: one CTA owns 4 batch rows for all T. Thread computes
// gates r0=tid, r1=tid+256. Whh rows 0..255 in smem (padded stride 132,
// conflict-free float4 reads); rows 256..511 streamed from L2.
// =====================================================================
#define WPAD 132
#define REC_SMEM (256 * WPAD * 4 + 512 * 4 * 2 + 4 * GG * 4)
__global__ void __launch_bounds__(256) lstm_rec(const float* __restrict__ xp,
                                                const float* __restrict__ Whh,
                                                float* __restrict__ hout) {
    extern __shared__ float sm[];
    float* w_s = sm;                     // [256][WPAD]
    float* h_s = w_s + 256 * WPAD;       // [4][128]
    float* c_s = h_s + 512;              // [4][128]
    float* g_s = c_s + 512;              // [4][512]
    int tid = threadIdx.x;
    int b0 = blockIdx.x * 4;

    for (int l = tid; l < 256 * HH; l += 256) {
        int r = l >> 7, k = l & 127;
        w_s[r * WPAD + k] = Whh[r * HH + k];
    }
    for (int l = tid; l < 512; l += 256) { h_s[l] = 0.0f; c_s[l] = 0.0f; }
    __syncthreads();

    const float* wg = Whh + (size_t)(256 + tid) * HH;   // row tid+256
    const float* w0p = &w_s[tid * WPAD];

    for (int t = 0; t < TT; t++) {
        const float* xpt = xp + ((size_t)t * BB + b0) * GG;
        float acc0[4], acc1[4];
#pragma unroll
        for (int bb = 0; bb < 4; bb++) {
            acc0[bb] = xpt[bb * GG + tid];
            acc1[bb] = xpt[bb * GG + 256 + tid];
        }
#pragma unroll 4
        for (int k = 0; k < HH; k += 4) {
            float4 w0 = *(const float4*)(w0p + k);
            float4 w1 = __ldg((const float4*)(wg + k));
#pragma unroll
            for (int bb = 0; bb < 4; bb++) {
                float4 hb = *(const float4*)&h_s[bb * HH + k];
                acc0[bb] += hb.x * w0.x + hb.y * w0.y + hb.z * w0.z + hb.w * w0.w;
                acc1[bb] += hb.x * w1.x + hb.y * w1.y + hb.z * w1.z + hb.w * w1.w;
            }
        }
#pragma unroll
        for (int bb = 0; bb < 4; bb++) {
            g_s[bb * GG + tid]       = acc0[bb];
            g_s[bb * GG + 256 + tid] = acc1[bb];
        }
        __syncthreads();
#pragma unroll
        for (int ii = 0; ii < 2; ii++) {
            int cidx = tid + ii * 256;           // = bb*128 + hh
            int bb = cidx >> 7, hh = cidx & 127;
            float gi = g_s[bb * GG + hh];
            float gf = g_s[bb * GG + 128 + hh];
            float gc = g_s[bb * GG + 256 + hh];
            float go = g_s[bb * GG + 384 + hh];
            float cc = sigf(gf) * c_s[cidx] + sigf(gi) * tanhf(gc);
            float h  = sigf(go) * tanhf(cc);
            c_s[cidx] = cc;
            h_s[cidx] = h;
            hout[((size_t)t * BB + b0 + bb) * HH + hh] = h;
        }
        __syncthreads();
    }
}

// ---------------- attn[n] = sum_h tanh(tmp[n,h]) * v[h] ----------------
__global__ void __launch_bounds__(256) attn_kernel(const float* __restrict__ tmp,
                                                   const float* __restrict__ v) {
    int warp = threadIdx.x >> 5, lane = threadIdx.x & 31;
    int n = blockIdx.x * 8 + warp;
    const float* row = tmp + (size_t)n * HH;
    float s = 0.0f;
#pragma unroll
    for (int j = lane; j < HH; j += 32) s += tanhf(row[j]) * v[j];
#pragma unroll
    for (int o = 16; o; o >>= 1) s += __shfl_xor_sync(0xffffffffu, s, o);
    if (lane == 0) g_attn[n] = s;
}

// ---------------- softmax over T + weighted pool ----------------
__global__ void __launch_bounds__(128) pool_kernel() {
    int b = blockIdx.x;
    int tid = threadIdx.x;
    __shared__ float wt[TT];
    __shared__ float red[128];
    float a = (tid < TT) ? g_attn[tid * BB + b] : -1e30f;
    red[tid] = a;
    __syncthreads();
    for (int s = 64; s; s >>= 1) {
        if (tid < s) red[tid] = fmaxf(red[tid], red[tid + s]);
        __syncthreads();
    }
    float mx = red[0];
    __syncthreads();
    float e = (tid < TT) ? expf(a - mx) : 0.0f;
    red[tid] = e;
    __syncthreads();
    for (int s = 64; s; s >>= 1) {
        if (tid < s) red[tid] += red[tid + s];
        __syncthreads();
    }
    float inv = 1.0f / red[0];
    if (tid < TT) wt[tid] = e * inv;
    __syncthreads();
    float acc = 0.0f;
#pragma unroll 4
    for (int t = 0; t < TT; t++)
        acc += wt[t] * g_h2[((size_t)t * BB + b) * HH + tid];
    g_pooled[b * HH + tid] = acc;
}

// ---------------- head ----------------
__global__ void __launch_bounds__(64) head_kernel(const float* __restrict__ W1,
                                                  const float* __restrict__ b1,
                                                  const float* __restrict__ W2,
                                                  const float* __restrict__ b2,
                                                  float* __restrict__ out) {
    int b = blockIdx.x;
    int tid = threadIdx.x;
    __shared__ float p[HH];
    __shared__ float hdn[64];
    for (int l = tid; l < HH; l += 64) p[l] = g_pooled[b * HH + l];
    __syncthreads();
    float acc = b1[tid];
#pragma unroll 8
    for (int k = 0; k < HH; k++) acc += p[k] * W1[tid * HH + k];
    hdn[tid] = acc;
    __syncthreads();
    if (tid < NC) {
        float o = b2[tid];
#pragma unroll
        for (int k = 0; k < 64; k++) o += hdn[k] * W2[tid * 64 + k];
        out[b * NC + tid] = o;
    }
}

// ---------------- host ----------------
extern "C" void kernel_launch(void* const* d_in, const int* in_sizes, int n_in,
                              void* d_out, int out_size) {
    const float* x      = (const float*)d_in[0];
    const float* conv_w = (const float*)d_in[1];
    const float* conv_b = (const float*)d_in[2];
    const float* Wih0   = (const float*)d_in[3];
    const float* Whh0   = (const float*)d_in[4];
    const float* bih0   = (const float*)d_in[5];
    const float* bhh0   = (const float*)d_in[6];
    const float* Wih1   = (const float*)d_in[7];
    const float* Whh1   = (const float*)d_in[8];
    const float* bih1   = (const float*)d_in[9];
    const float* bhh1   = (const float*)d_in[10];
    const float* W_att  = (const float*)d_in[11];
    const float* b_att  = (const float*)d_in[12];
    const float* v_att  = (const float*)d_in[13];
    const float* W1     = (const float*)d_in[14];
    const float* b1     = (const float*)d_in[15];
    const float* W2     = (const float*)d_in[16];
    const float* b2     = (const float*)d_in[17];
    float* out = (float*)d_out;

    float *seq_p, *xp_p, *h1_p, *h2_p, *wattT_p;
    cudaGetSymbolAddress((void**)&seq_p,   g_seq);
    cudaGetSymbolAddress((void**)&xp_p,    g_xp);
    cudaGetSymbolAddress((void**)&h1_p,    g_h1);
    cudaGetSymbolAddress((void**)&h2_p,    g_h2);
    cudaGetSymbolAddress((void**)&wattT_p, g_wattT);

    static int s_init = 0;
    if (!s_init) {
        cudaFuncSetAttribute(conv_kernel, cudaFuncAttributeMaxDynamicSharedMemorySize,
                             812 * 40 * 4);
        cudaFuncSetAttribute(lstm_rec, cudaFuncAttributeMaxDynamicSharedMemorySize,
                             REC_SMEM);
        s_init = 1;
    }

    // W_att transpose (128x128)
    transpose_kernel<<<(HH * HH + 255) / 256, 256>>>(W_att, wattT_p, HH, HH);

    // conv -> seq
    conv_kernel<<<BB, 256, 812 * 40 * 4>>>(x, conv_w, conv_b);

    // x_proj layer 0: (51200,576) @ Wih0^T + bih0 + bhh0
    gemm128<<<dim3(GG / 128, (TT * BB) / 128), 256>>>(seq_p, Wih0, bih0, bhh0, xp_p,
                                                      TT * BB, GG, FF);
    lstm_rec<<<BB / 4, 256, REC_SMEM>>>(xp_p, Whh0, h1_p);

    // x_proj layer 1
    gemm128<<<dim3(GG / 128, (TT * BB) / 128), 256>>>(h1_p, Wih1, bih1, bhh1, xp_p,
                                                      TT * BB, GG, HH);
    lstm_rec<<<BB / 4, 256, REC_SMEM>>>(xp_p, Whh1, h2_p);

    // attention pre-activation: (51200,128) @ wattT + b_att
    gemm128<<<dim3(HH / 128, (TT * BB) / 128), 256>>>(h2_p, wattT_p, b_att, nullptr,
                                                      xp_p, TT * BB, HH, HH);
    attn_kernel<<<(TT * BB) / 8, 256>>>(xp_p, v_att);
    pool_kernel<<<BB, 128>>>();
    head_kernel<<<BB, 64>>>(W1, b1, W2, b2, out);
}

// round 4
// speedup vs baseline: 1.5416x; 1.5416x over previous
#include <cuda_runtime.h>
#include <cuda_bf16.h>
#include <math.h>

// ---------------- problem constants ----------------
#define TT   100      // time steps after conv
#define BB   512      // batch
#define WW   18       // conv output width
#define CC   32       // conv channels
#define FF   576      // WW*CC lstm input features
#define HH   128      // hidden
#define GG   512      // 4*HH gates
#define NC   12       // classes

// ---------------- device scratch ----------------
__device__ float g_seq [TT * BB * FF];
__device__ float g_xp  [TT * BB * GG];
__device__ float g_h1  [TT * BB * HH];
__device__ float g_h2  [TT * BB * HH];
__device__ float g_wattT[HH * HH];
__device__ float g_attn [TT * BB];
__device__ float g_pooled[BB * HH];

__device__ __forceinline__ float sigf(float x) { return 1.0f / (1.0f + expf(-x)); }

// =====================================================================
// Conv: one block per batch image. Whole image in smem (812*40*4=127KB).
// Lane = channel (32). Each warp processes pairs of time steps (t0,t0+1)
// which share 12 of their 28 input rows. Per-channel weights live in
// registers (100 per thread). Patch loads broadcast across the 32 lanes.
// =====================================================================
__global__ void __launch_bounds__(256, 1) conv_kernel(const float* __restrict__ x,
                                                      const float* __restrict__ cw,
                                                      const float* __restrict__ cb) {
    extern __shared__ float s_img[];   // [812][40]
    int b = blockIdx.x;
    int tid = threadIdx.x;
    int wid = tid >> 5, lane = tid & 31;
    int c = lane;

    // load image (coalesced float4)
    const float4* src = (const float4*)(x + (size_t)b * 812 * 40);
    float4* dst = (float4*)s_img;
    for (int i = tid; i < 812 * 10; i += 256) dst[i] = src[i];

    // per-channel weights + bias into registers
    float wr[100];
#pragma unroll
    for (int i = 0; i < 100; i++) wr[i] = __ldg(&cw[c * 100 + i]);
    float bv = __ldg(&cb[c]);
    __syncthreads();

    for (int p = wid; p < 50; p += 8) {          // t0 = 2p, t1 = 2p+1
        int base_row = 16 * p;
        float acc[2][18];
#pragma unroll
        for (int w = 0; w < 18; w++) { acc[0][w] = bv; acc[1][w] = bv; }

#pragma unroll
        for (int rr = 0; rr < 28; rr++) {
            const float* prow = &s_img[(base_row + rr) * 40];
#pragma unroll
            for (int j = 0; j < 40; j++) {
                float pv = prow[j];
#pragma unroll
                for (int kw = 0; kw < 5; kw++) {
                    int d = j - kw;
                    if (d >= 0 && (d & 1) == 0) {
                        int w = d >> 1;
                        if (w < 18) {
                            if (rr < 20) acc[0][w] += wr[rr * 5 + kw] * pv;
                            if (rr >= 8) acc[1][w] += wr[(rr - 8) * 5 + kw] * pv;
                        }
                    }
                }
            }
        }
#pragma unroll
        for (int ts = 0; ts < 2; ts++) {
            int t = 2 * p + ts;
            float* out = &g_seq[((size_t)t * BB + b) * FF];
#pragma unroll
            for (int w = 0; w < 18; w++)
                out[w * 32 + c] = fmaxf(acc[ts][w], 0.0f);
        }
    }
}

// ---------------- generic transpose (used for W_att only) ----------------
__global__ void transpose_kernel(const float* __restrict__ in, float* __restrict__ out,
                                 int rows, int cols) {
    int idx = blockIdx.x * 256 + threadIdx.x;
    if (idx < rows * cols) {
        int r = idx / cols, c = idx % cols;
        out[c * rows + r] = in[idx];
    }
}

// =====================================================================
// fp32 SGEMM: C[M,N] = A[M,K] @ B[N,K]^T + bias0 + bias1
// 128x128 tile, BK=16, 8x8 micro-tile, double-buffered smem, ONE sync
// per k-tile. NO minBlocks reg cap (round-2's cap caused spills).
// Requires M%128==0, N%128==0, K%16==0.
// =====================================================================
__global__ void __launch_bounds__(256) gemm128(const float* __restrict__ A,
                                               const float* __restrict__ Bm,
                                               const float* __restrict__ bias0,
                                               const float* __restrict__ bias1,
                                               float* __restrict__ C,
                                               int M, int N, int K) {
    __shared__ float As[2][16][128];
    __shared__ float Bs[2][16][128];
    int tid = threadIdx.x;
    int tx = tid & 15, ty = tid >> 4;
    int bm = blockIdx.y * 128, bn = blockIdx.x * 128;

    int r0 = tid >> 2, kq = (tid & 3) << 2;
    int r1 = r0 + 64;
    const float* Ap0 = A + (size_t)(bm + r0) * K + kq;
    const float* Ap1 = A + (size_t)(bm + r1) * K + kq;
    const float* Bp0 = Bm + (size_t)(bn + r0) * K + kq;
    const float* Bp1 = Bm + (size_t)(bn + r1) * K + kq;

    float4 a0 = *(const float4*)Ap0;
    float4 a1 = *(const float4*)Ap1;
    float4 b0 = *(const float4*)Bp0;
    float4 b1 = *(const float4*)Bp1;

    // stage tile 0 into buffer 0
    As[0][kq + 0][r0] = a0.x; As[0][kq + 1][r0] = a0.y; As[0][kq + 2][r0] = a0.z; As[0][kq + 3][r0] = a0.w;
    As[0][kq + 0][r1] = a1.x; As[0][kq + 1][r1] = a1.y; As[0][kq + 2][r1] = a1.z; As[0][kq + 3][r1] = a1.w;
    Bs[0][kq + 0][r0] = b0.x; Bs[0][kq + 1][r0] = b0.y; Bs[0][kq + 2][r0] = b0.z; Bs[0][kq + 3][r0] = b0.w;
    Bs[0][kq + 0][r1] = b1.x; Bs[0][kq + 1][r1] = b1.y; Bs[0][kq + 2][r1] = b1.z; Bs[0][kq + 3][r1] = b1.w;
    __syncthreads();

    float acc[8][8];
#pragma unroll
    for (int i = 0; i < 8; i++)
#pragma unroll
        for (int j = 0; j < 8; j++) acc[i][j] = 0.0f;

    int buf = 0;
    for (int kt = 0; kt < K; kt += 16) {
        bool more = (kt + 16) < K;
        if (more) {
            a0 = *(const float4*)(Ap0 + kt + 16);
            a1 = *(const float4*)(Ap1 + kt + 16);
            b0 = *(const float4*)(Bp0 + kt + 16);
            b1 = *(const float4*)(Bp1 + kt + 16);
        }

#pragma unroll
        for (int kk = 0; kk < 16; kk++) {
            float4 x0 = *(const float4*)&As[buf][kk][ty * 8];
            float4 x1 = *(const float4*)&As[buf][kk][ty * 8 + 4];
            float4 y0 = *(const float4*)&Bs[buf][kk][tx * 8];
            float4 y1 = *(const float4*)&Bs[buf][kk][tx * 8 + 4];
            float xa[8] = {x0.x, x0.y, x0.z, x0.w, x1.x, x1.y, x1.z, x1.w};
            float yb[8] = {y0.x, y0.y, y0.z, y0.w, y1.x, y1.y, y1.z, y1.w};
#pragma unroll
            for (int i = 0; i < 8; i++)
#pragma unroll
                for (int j = 0; j < 8; j++) acc[i][j] += xa[i] * yb[j];
        }

        if (more) {
            int nb = buf ^ 1;
            As[nb][kq + 0][r0] = a0.x; As[nb][kq + 1][r0] = a0.y; As[nb][kq + 2][r0] = a0.z; As[nb][kq + 3][r0] = a0.w;
            As[nb][kq + 0][r1] = a1.x; As[nb][kq + 1][r1] = a1.y; As[nb][kq + 2][r1] = a1.z; As[nb][kq + 3][r1] = a1.w;
            Bs[nb][kq + 0][r0] = b0.x; Bs[nb][kq + 1][r0] = b0.y; Bs[nb][kq + 2][r0] = b0.z; Bs[nb][kq + 3][r0] = b0.w;
            Bs[nb][kq + 0][r1] = b1.x; Bs[nb][kq + 1][r1] = b1.y; Bs[nb][kq + 2][r1] = b1.z; Bs[nb][kq + 3][r1] = b1.w;
        }
        __syncthreads();
        buf ^= 1;
    }

    float bc[8];
#pragma unroll
    for (int j = 0; j < 8; j++) {
        int col = bn + tx * 8 + j;
        float v = 0.0f;
        if (bias0) v += bias0[col];
        if (bias1) v += bias1[col];
        bc[j] = v;
    }
#pragma unroll
    for (int i = 0; i < 8; i++) {
        int row = bm + ty * 8 + i;
        float* cp = C + (size_t)row * N + bn + tx * 8;
        float4 o0 = make_float4(acc[i][0] + bc[0], acc[i][1] + bc[1],
                                acc[i][2] + bc[2], acc[i][3] + bc[3]);
        float4 o1 = make_float4(acc[i][4] + bc[4], acc[i][5] + bc[5],
                                acc[i][6] + bc[6], acc[i][7] + bc[7]);
        *(float4*)cp = o0;
        *(float4*)(cp + 4) = o1;
    }
}

// =====================================================================
// LSTM recurrence: one CTA owns 4 batch rows for all T. Thread computes
// gates r0=tid, r1=tid+256. Whh rows 0..255 in smem (padded stride 132,
// conflict-free float4 reads); rows 256..511 streamed from L2.
// =====================================================================
#define WPAD 132
#define REC_SMEM (256 * WPAD * 4 + 512 * 4 * 2 + 4 * GG * 4)
__global__ void __launch_bounds__(256) lstm_rec(const float* __restrict__ xp,
                                                const float* __restrict__ Whh,
                                                float* __restrict__ hout) {
    extern __shared__ float sm[];
    float* w_s = sm;                     // [256][WPAD]
    float* h_s = w_s + 256 * WPAD;       // [4][128]
    float* c_s = h_s + 512;              // [4][128]
    float* g_s = c_s + 512;              // [4][512]
    int tid = threadIdx.x;
    int b0 = blockIdx.x * 4;

    for (int l = tid; l < 256 * HH; l += 256) {
        int r = l >> 7, k = l & 127;
        w_s[r * WPAD + k] = Whh[r * HH + k];
    }
    for (int l = tid; l < 512; l += 256) { h_s[l] = 0.0f; c_s[l] = 0.0f; }
    __syncthreads();

    const float* wg = Whh + (size_t)(256 + tid) * HH;   // row tid+256
    const float* w0p = &w_s[tid * WPAD];

    for (int t = 0; t < TT; t++) {
        const float* xpt = xp + ((size_t)t * BB + b0) * GG;
        float acc0[4], acc1[4];
#pragma unroll
        for (int bb = 0; bb < 4; bb++) {
            acc0[bb] = xpt[bb * GG + tid];
            acc1[bb] = xpt[bb * GG + 256 + tid];
        }
#pragma unroll 4
        for (int k = 0; k < HH; k += 4) {
            float4 w0 = *(const float4*)(w0p + k);
            float4 w1 = __ldg((const float4*)(wg + k));
#pragma unroll
            for (int bb = 0; bb < 4; bb++) {
                float4 hb = *(const float4*)&h_s[bb * HH + k];
                acc0[bb] += hb.x * w0.x + hb.y * w0.y + hb.z * w0.z + hb.w * w0.w;
                acc1[bb] += hb.x * w1.x + hb.y * w1.y + hb.z * w1.z + hb.w * w1.w;
            }
        }
#pragma unroll
        for (int bb = 0; bb < 4; bb++) {
            g_s[bb * GG + tid]       = acc0[bb];
            g_s[bb * GG + 256 + tid] = acc1[bb];
        }
        __syncthreads();
#pragma unroll
        for (int ii = 0; ii < 2; ii++) {
            int cidx = tid + ii * 256;           // = bb*128 + hh
            int bb = cidx >> 7, hh = cidx & 127;
            float gi = g_s[bb * GG + hh];
            float gf = g_s[bb * GG + 128 + hh];
            float gc = g_s[bb * GG + 256 + hh];
            float go = g_s[bb * GG + 384 + hh];
            float cc = sigf(gf) * c_s[cidx] + sigf(gi) * tanhf(gc);
            float h  = sigf(go) * tanhf(cc);
            c_s[cidx] = cc;
            h_s[cidx] = h;
            hout[((size_t)t * BB + b0 + bb) * HH + hh] = h;
        }
        __syncthreads();
    }
}

// ---------------- attn[n] = sum_h tanh(tmp[n,h]) * v[h] ----------------
__global__ void __launch_bounds__(256) attn_kernel(const float* __restrict__ tmp,
                                                   const float* __restrict__ v) {
    int warp = threadIdx.x >> 5, lane = threadIdx.x & 31;
    int n = blockIdx.x * 8 + warp;
    const float* row = tmp + (size_t)n * HH;
    float s = 0.0f;
#pragma unroll
    for (int j = lane; j < HH; j += 32) s += tanhf(row[j]) * v[j];
#pragma unroll
    for (int o = 16; o; o >>= 1) s += __shfl_xor_sync(0xffffffffu, s, o);
    if (lane == 0) g_attn[n] = s;
}

// ---------------- softmax over T + weighted pool ----------------
__global__ void __launch_bounds__(128) pool_kernel() {
    int b = blockIdx.x;
    int tid = threadIdx.x;
    __shared__ float wt[TT];
    __shared__ float red[128];
    float a = (tid < TT) ? g_attn[tid * BB + b] : -1e30f;
    red[tid] = a;
    __syncthreads();
    for (int s = 64; s; s >>= 1) {
        if (tid < s) red[tid] = fmaxf(red[tid], red[tid + s]);
        __syncthreads();
    }
    float mx = red[0];
    __syncthreads();
    float e = (tid < TT) ? expf(a - mx) : 0.0f;
    red[tid] = e;
    __syncthreads();
    for (int s = 64; s; s >>= 1) {
        if (tid < s) red[tid] += red[tid + s];
        __syncthreads();
    }
    float inv = 1.0f / red[0];
    if (tid < TT) wt[tid] = e * inv;
    __syncthreads();
    float acc = 0.0f;
#pragma unroll 4
    for (int t = 0; t < TT; t++)
        acc += wt[t] * g_h2[((size_t)t * BB + b) * HH + tid];
    g_pooled[b * HH + tid] = acc;
}

// ---------------- head ----------------
__global__ void __launch_bounds__(64) head_kernel(const float* __restrict__ W1,
                                                  const float* __restrict__ b1,
                                                  const float* __restrict__ W2,
                                                  const float* __restrict__ b2,
                                                  float* __restrict__ out) {
    int b = blockIdx.x;
    int tid = threadIdx.x;
    __shared__ float p[HH];
    __shared__ float hdn[64];
    for (int l = tid; l < HH; l += 64) p[l] = g_pooled[b * HH + l];
    __syncthreads();
    float acc = b1[tid];
#pragma unroll 8
    for (int k = 0; k < HH; k++) acc += p[k] * W1[tid * HH + k];
    hdn[tid] = acc;
    __syncthreads();
    if (tid < NC) {
        float o = b2[tid];
#pragma unroll
        for (int k = 0; k < 64; k++) o += hdn[k] * W2[tid * 64 + k];
        out[b * NC + tid] = o;
    }
}

// ---------------- host ----------------
extern "C" void kernel_launch(void* const* d_in, const int* in_sizes, int n_in,
                              void* d_out, int out_size) {
    const float* x      = (const float*)d_in[0];
    const float* conv_w = (const float*)d_in[1];
    const float* conv_b = (const float*)d_in[2];
    const float* Wih0   = (const float*)d_in[3];
    const float* Whh0   = (const float*)d_in[4];
    const float* bih0   = (const float*)d_in[5];
    const float* bhh0   = (const float*)d_in[6];
    const float* Wih1   = (const float*)d_in[7];
    const float* Whh1   = (const float*)d_in[8];
    const float* bih1   = (const float*)d_in[9];
    const float* bhh1   = (const float*)d_in[10];
    const float* W_att  = (const float*)d_in[11];
    const float* b_att  = (const float*)d_in[12];
    const float* v_att  = (const float*)d_in[13];
    const float* W1     = (const float*)d_in[14];
    const float* b1     = (const float*)d_in[15];
    const float* W2     = (const float*)d_in[16];
    const float* b2     = (const float*)d_in[17];
    float* out = (float*)d_out;

    float *seq_p, *xp_p, *h1_p, *h2_p, *wattT_p;
    cudaGetSymbolAddress((void**)&seq_p,   g_seq);
    cudaGetSymbolAddress((void**)&xp_p,    g_xp);
    cudaGetSymbolAddress((void**)&h1_p,    g_h1);
    cudaGetSymbolAddress((void**)&h2_p,    g_h2);
    cudaGetSymbolAddress((void**)&wattT_p, g_wattT);

    cudaFuncSetAttribute(conv_kernel, cudaFuncAttributeMaxDynamicSharedMemorySize,
                         812 * 40 * 4);
    cudaFuncSetAttribute(lstm_rec, cudaFuncAttributeMaxDynamicSharedMemorySize,
                         REC_SMEM);

    // W_att transpose (128x128)
    transpose_kernel<<<(HH * HH + 255) / 256, 256>>>(W_att, wattT_p, HH, HH);

    // conv -> seq
    conv_kernel<<<BB, 256, 812 * 40 * 4>>>(x, conv_w, conv_b);

    // x_proj layer 0: (51200,576) @ Wih0^T + bih0 + bhh0
    gemm128<<<dim3(GG / 128, (TT * BB) / 128), 256>>>(seq_p, Wih0, bih0, bhh0, xp_p,
                                                      TT * BB, GG, FF);
    lstm_rec<<<BB / 4, 256, REC_SMEM>>>(xp_p, Whh0, h1_p);

    // x_proj layer 1
    gemm128<<<dim3(GG / 128, (TT * BB) / 128), 256>>>(h1_p, Wih1, bih1, bhh1, xp_p,
                                                      TT * BB, GG, HH);
    lstm_rec<<<BB / 4, 256, REC_SMEM>>>(xp_p, Whh1, h2_p);

    // attention pre-activation: (51200,128) @ wattT + b_att
    gemm128<<<dim3(HH / 128, (TT * BB) / 128), 256>>>(h2_p, wattT_p, b_att, nullptr,
                                                      xp_p, TT * BB, HH, HH);
    attn_kernel<<<(TT * BB) / 8, 256>>>(xp_p, v_att);
    pool_kernel<<<BB, 128>>>();
    head_kernel<<<BB, 64>>>(W1, b1, W2, b2, out);
}